// round 11
// baseline (speedup 1.0000x reference)
#include <cuda_runtime.h>
#include <cuda_fp16.h>
#include <math.h>
#include <stdint.h>

#define B_   2
#define S_   2048
#define D_   2048
#define HQ_  16
#define HKV_ 4
#define HD_  128
#define WIN_ 1024
#define EPS_ 1e-8f
#define MROWS (B_ * S_)    // 4096

// ---------------- scratch (device globals) ----------------
__device__ float g_q[MROWS * HQ_ * HD_];
__device__ float g_k[MROWS * HKV_ * HD_];

__device__ __half g_qq[MROWS * D_];
__device__ __half g_kk[MROWS * 512];
__device__ __half g_vv[MROWS * 512];
__device__ __half g_oo[MROWS * D_];

__device__ __half g_ax[MROWS * D_];
__device__ __half g_wqkvT[3072 * D_];
__device__ __half g_woT[D_ * D_];

__device__ __forceinline__ uint32_t smem_u32(const void* p) {
    uint32_t a;
    asm("{ .reg .u64 t; cvta.to.shared.u64 t, %1; cvt.u32.u64 %0, t; }" : "=r"(a) : "l"(p));
    return a;
}

#define LDSM4(r0, r1, r2, r3, addr) \
    asm volatile("ldmatrix.sync.aligned.m8n8.x4.shared.b16 {%0,%1,%2,%3}, [%4];" \
                 : "=r"(r0), "=r"(r1), "=r"(r2), "=r"(r3) : "r"(addr))
#define LDSM4T(r0, r1, r2, r3, addr) \
    asm volatile("ldmatrix.sync.aligned.m8n8.x4.trans.shared.b16 {%0,%1,%2,%3}, [%4];" \
                 : "=r"(r0), "=r"(r1), "=r"(r2), "=r"(r3) : "r"(addr))

#define MMA_F16(c0, c1, c2, c3, a0, a1, a2, a3, b0, b1) \
    asm volatile("mma.sync.aligned.m16n8k16.row.col.f32.f16.f16.f32 " \
                 "{%0,%1,%2,%3}, {%4,%5,%6,%7}, {%8,%9}, {%0,%1,%2,%3};" \
                 : "+f"(c0), "+f"(c1), "+f"(c2), "+f"(c3) \
                 : "r"(a0), "r"(a1), "r"(a2), "r"(a3), "r"(b0), "r"(b1))

__device__ __forceinline__ void cp16(uint32_t dst, const void* src) {
    asm volatile("cp.async.cg.shared.global [%0], [%1], 16;" :: "r"(dst), "l"(src));
}
__device__ __forceinline__ void cp_commit() { asm volatile("cp.async.commit_group;"); }
__device__ __forceinline__ void cp_wait1() { asm volatile("cp.async.wait_group 1;"); }
__device__ __forceinline__ void cp_wait0() { asm volatile("cp.async.wait_group 0;"); }

__device__ __forceinline__ uint32_t packh(float lo, float hi) {
    __half2 h = __floats2half2_rn(lo, hi);
    return *(uint32_t*)&h;
}

__device__ __forceinline__ float fexp2(float x) {
    float r;
    asm("ex2.approx.ftz.f32 %0, %1;" : "=f"(r) : "f"(x));
    return r;
}

// =================================================================================
// prep kernels
// =================================================================================
__global__ void aconv(const float4* __restrict__ src, __half* __restrict__ dst, int n4) {
    int i = blockIdx.x * blockDim.x + threadIdx.x;
    if (i >= n4) return;
    float4 v = src[i];
    uint32_t* dp = (uint32_t*)(dst + (size_t)i * 4);
    dp[0] = packh(v.x, v.y);
    dp[1] = packh(v.z, v.w);
}

// All 4 weight transposes in ONE launch. Tiles 32x32; dst K-stride always 2048.
// regions: [0,4096) Wq -> wqkvT+0 ; [4096,5120) Wk -> wqkvT+2048*2048 ;
//          [5120,6144) Wv -> wqkvT+2560*2048 ; [6144,10240) Wo -> woT.
__global__ void wconv_all(const float* __restrict__ Wq, const float* __restrict__ Wk,
                          const float* __restrict__ Wv, const float* __restrict__ Wo,
                          __half* __restrict__ wqkvT, __half* __restrict__ woT) {
    __shared__ float t[32][33];
    int bt = blockIdx.x;
    const float* W;
    __half* T;
    int N, ntiles_x;
    if (bt < 4096)       { W = Wq; T = wqkvT;                          N = 2048; ntiles_x = 64; }
    else if (bt < 5120)  { W = Wk; T = wqkvT + (size_t)2048 * D_; bt -= 4096; N = 512; ntiles_x = 16; }
    else if (bt < 6144)  { W = Wv; T = wqkvT + (size_t)2560 * D_; bt -= 5120; N = 512; ntiles_x = 16; }
    else                 { W = Wo; T = woT;                      bt -= 6144; N = 2048; ntiles_x = 64; }
    int n0 = (bt % ntiles_x) * 32, k0 = (bt / ntiles_x) * 32;
    int tx = threadIdx.x, ty = threadIdx.y;
#pragma unroll
    for (int i = 0; i < 4; i++) {
        int k = ty + i * 8;
        t[k][tx] = W[(size_t)(k0 + k) * N + n0 + tx];
    }
    __syncthreads();
#pragma unroll
    for (int i = 0; i < 4; i++) {
        int r = ty + i * 8;
        T[(size_t)(n0 + r) * D_ + k0 + tx] = __float2half_rn(t[tx][r]);
    }
}

// =================================================================================
// mma.sync fp16 GEMM: C = A[M,K] @ Bt[N,K]^T, fp32 accum.
// 128x256x64 block tile, 3-stage cp.async pipeline, 8 warps (2m x 4n, 64x64 each).
// MODE 0: fp32 C.   MODE 1: fused QKV epilogue (N=3072; routes to g_q/g_k/g_vv).
// =================================================================================
#define GSTRIDE 72
#define GATILE  (128 * GSTRIDE * 2)     // 18432 B (A: 128 rows)
#define GBTILE  (256 * GSTRIDE * 2)     // 36864 B (B: 256 rows)
#define GSTAGE  (GATILE + GBTILE)       // 55296 B
#define GEMM_SMEM (3 * GSTAGE)          // 165888 B

__device__ __forceinline__ void g_load_stage(
    uint32_t sdst, const __half* __restrict__ A, const __half* __restrict__ Bt,
    int m0, int n0, int kc, int K, int tid) {
    {   // A: 128 rows -> 1024 chunks
        const __half* g = A + (size_t)m0 * K + kc * 64;
#pragma unroll
        for (int i = 0; i < 4; i++) {
            int ch  = tid + 256 * i;
            int row = ch >> 3;
            int off = (ch & 7) * 8;
            cp16(sdst + row * (GSTRIDE * 2) + off * 2, g + (size_t)row * K + off);
        }
    }
    {   // B: 256 rows -> 2048 chunks
        const __half* g = Bt + (size_t)n0 * K + kc * 64;
        uint32_t db = sdst + GATILE;
#pragma unroll
        for (int i = 0; i < 8; i++) {
            int ch  = tid + 256 * i;
            int row = ch >> 3;
            int off = (ch & 7) * 8;
            cp16(db + row * (GSTRIDE * 2) + off * 2, g + (size_t)row * K + off);
        }
    }
}

template<int MODE>
__global__ __launch_bounds__(256, 1)
void bgemm(const __half* __restrict__ A, const __half* __restrict__ Bt,
           float* __restrict__ C, int M, int N, int K) {
    extern __shared__ char sm[];
    uint32_t sb = smem_u32(sm);
    int tid = threadIdx.x, lane = tid & 31, wid = tid >> 5;
    int n0 = blockIdx.x * 256, m0 = blockIdx.y * 128;
    int wm = (wid >> 2) * 64;
    int wn = (wid & 3) * 64;

    float acc[4][8][4];
#pragma unroll
    for (int i = 0; i < 4; i++)
#pragma unroll
        for (int j = 0; j < 8; j++)
#pragma unroll
            for (int c = 0; c < 4; c++) acc[i][j][c] = 0.f;

    int a_row = wm + (lane & 15);
    int a_kb  = (lane >> 4) * 16;
    int b_row = wn + (lane & 7) + ((lane >> 4) << 3);
    int b_kb  = ((lane >> 3) & 1) * 16;
    uint32_t aoff = (uint32_t)(a_row * (GSTRIDE * 2) + a_kb);
    uint32_t boff = (uint32_t)(b_row * (GSTRIDE * 2) + b_kb);

    int nk = K >> 6;
    g_load_stage(sb, A, Bt, m0, n0, 0, K, tid);
    cp_commit();
    g_load_stage(sb + GSTAGE, A, Bt, m0, n0, 1, K, tid);
    cp_commit();

    for (int kt = 0; kt < nk; kt++) {
        if (kt + 1 < nk) cp_wait1(); else cp_wait0();
        __syncthreads();

        uint32_t st = sb + (kt % 3) * GSTAGE;
#pragma unroll
        for (int ks = 0; ks < 4; ks++) {
            uint32_t ah[4][4];
#pragma unroll
            for (int mt = 0; mt < 4; mt++) {
                uint32_t adr = st + aoff + mt * 16 * (GSTRIDE * 2) + ks * 32;
                LDSM4(ah[mt][0], ah[mt][1], ah[mt][2], ah[mt][3], adr);
            }
            uint32_t bh[8][2];
#pragma unroll
            for (int ntg = 0; ntg < 4; ntg++) {
                uint32_t adr = st + GATILE + boff + ntg * 16 * (GSTRIDE * 2) + ks * 32;
                uint32_t r0, r1, r2, r3;
                LDSM4(r0, r1, r2, r3, adr);
                bh[ntg * 2][0] = r0; bh[ntg * 2][1] = r1;
                bh[ntg * 2 + 1][0] = r2; bh[ntg * 2 + 1][1] = r3;
            }
#pragma unroll
            for (int mt = 0; mt < 4; mt++)
#pragma unroll
                for (int nt = 0; nt < 8; nt++) {
                    float* c = acc[mt][nt];
                    MMA_F16(c[0], c[1], c[2], c[3],
                            ah[mt][0], ah[mt][1], ah[mt][2], ah[mt][3],
                            bh[nt][0], bh[nt][1]);
                }
        }

        if (kt + 2 < nk) {
            g_load_stage(sb + ((kt + 2) % 3) * GSTAGE, A, Bt, m0, n0, kt + 2, K, tid);
            cp_commit();
        }
    }

#pragma unroll
    for (int mt = 0; mt < 4; mt++) {
#pragma unroll
        for (int nt = 0; nt < 8; nt++) {
            int r = m0 + wm + mt * 16 + (lane >> 2);
            int cc = n0 + wn + nt * 8 + (lane & 3) * 2;
            float* c = acc[mt][nt];
            if (MODE == 1) {
                if (cc < 2048) {
                    *(float2*)&g_q[(size_t)r * 2048 + cc]       = make_float2(c[0], c[1]);
                    *(float2*)&g_q[(size_t)(r + 8) * 2048 + cc] = make_float2(c[2], c[3]);
                } else if (cc < 2560) {
                    int c2 = cc - 2048;
                    *(float2*)&g_k[(size_t)r * 512 + c2]       = make_float2(c[0], c[1]);
                    *(float2*)&g_k[(size_t)(r + 8) * 512 + c2] = make_float2(c[2], c[3]);
                } else {
                    int c2 = cc - 2560;
                    *(uint32_t*)&g_vv[(size_t)r * 512 + c2]       = packh(c[0], c[1]);
                    *(uint32_t*)&g_vv[(size_t)(r + 8) * 512 + c2] = packh(c[2], c[3]);
                }
            } else {
                *(float2*)&C[(size_t)r * N + cc]       = make_float2(c[0], c[1]);
                *(float2*)&C[(size_t)(r + 8) * N + cc] = make_float2(c[2], c[3]);
            }
        }
    }
}

// =================================================================================
// RMSNorm + RoPE (unchanged)
// =================================================================================
__global__ void norm_rope_kernel(const float* __restrict__ qw,
                                 const float* __restrict__ kw,
                                 const float* __restrict__ cos_t,
                                 const float* __restrict__ sin_t) {
    int wid  = (blockIdx.x * blockDim.x + threadIdx.x) >> 5;
    int lane = threadIdx.x & 31;
    const int NQ   = B_ * S_ * HQ_;
    const int NTOT = NQ + B_ * S_ * HKV_;
    if (wid >= NTOT) return;

    const float FOLD = 0.08838834764831845f * 1.4426950408889634f;

    bool isq = wid < NQ;
    const float* base;
    int s;
    const float* w;
    float fold;
    __half* out;
    if (isq) {
        base = g_q + (size_t)wid * HD_;
        out  = g_qq + (size_t)wid * HD_;
        s = (wid / HQ_) % S_;
        w = qw;
        fold = FOLD;
    } else {
        int r = wid - NQ;
        base = g_k + (size_t)r * HD_;
        out  = g_kk + (size_t)r * HD_;
        s = (r / HKV_) % S_;
        w = kw;
        fold = 1.0f;
    }

    float v0 = base[lane], v1 = base[lane + 32], v2 = base[lane + 64], v3 = base[lane + 96];
    float ss = v0 * v0 + v1 * v1 + v2 * v2 + v3 * v3;
#pragma unroll
    for (int o = 16; o > 0; o >>= 1) ss += __shfl_xor_sync(0xffffffff, ss, o);
    float inv = rsqrtf(ss * (1.0f / HD_) + EPS_);

    float x0 = v0 * inv * (1.f + w[lane]);
    float x1 = v1 * inv * (1.f + w[lane + 32]);
    float x2 = v2 * inv * (1.f + w[lane + 64]);
    float x3 = v3 * inv * (1.f + w[lane + 96]);

    const float* cr = cos_t + (size_t)s * HD_;
    const float* sr = sin_t + (size_t)s * HD_;
    out[lane]      = __float2half_rn((x0 * cr[lane]      - x2 * sr[lane])      * fold);
    out[lane + 32] = __float2half_rn((x1 * cr[lane + 32] - x3 * sr[lane + 32]) * fold);
    out[lane + 64] = __float2half_rn((x2 * cr[lane + 64] + x0 * sr[lane + 64]) * fold);
    out[lane + 96] = __float2half_rn((x3 * cr[lane + 96] + x1 * sr[lane + 96]) * fold);
}

// =================================================================================
// Tensor-core flash attention (R10 structure; tree-reduced softmax).
// =================================================================================
#define ASTR 272
#define AMAT (128 * ASTR)
#define ATTN_SMEM (5 * AMAT)

__device__ __forceinline__ void a_load_mat(uint32_t sdst, const __half* __restrict__ g,
                                           int rowstride, int tid) {
#pragma unroll
    for (int i = 0; i < 8; i++) {
        int ch = tid + 256 * i;
        int row = ch >> 4, c = ch & 15;
        cp16(sdst + row * ASTR + c * 16, g + (size_t)row * rowstride + c * 8);
    }
}

__global__ __launch_bounds__(256, 1)
void attn_kernel() {
    extern __shared__ char sm[];
    uint32_t sb = smem_u32(sm);
    const uint32_t sQ = sb;
    const uint32_t sK[2] = { sb + 1 * AMAT, sb + 2 * AMAT };
    const uint32_t sV[2] = { sb + 3 * AMAT, sb + 4 * AMAT };

    int tid = threadIdx.x, l = tid & 31, wid = tid >> 5;
    int qt = gridDim.x - 1 - blockIdx.x;
    int h = blockIdx.y, b = blockIdx.z;
    int q0 = qt * 128;
    int kvh = h >> 2;
    int g4 = l >> 2, t4 = l & 3;

    int lo = q0 - WIN_; if (lo < 0) lo = 0;
    int kt0 = lo >> 7, kt1 = q0 >> 7;
    bool has_edge = (q0 >= WIN_);

    const size_t kvbase = (size_t)(b * S_) * 512 + kvh * HD_;

    a_load_mat(sQ, g_qq + ((size_t)(b * S_ + q0)) * D_ + h * HD_, D_, tid);
    a_load_mat(sK[kt0 & 1], g_kk + kvbase + ((size_t)kt0 << 7) * 512, 512, tid);
    cp_commit();
    a_load_mat(sV[kt0 & 1], g_vv + kvbase + ((size_t)kt0 << 7) * 512, 512, tid);
    if (kt0 < kt1)
        a_load_mat(sK[(kt0 + 1) & 1], g_kk + kvbase + ((size_t)(kt0 + 1) << 7) * 512, 512, tid);
    cp_commit();

    float m_a = 0.f, m_b = 0.f, l_a = 0.f, l_b = 0.f;
    float o[16][4];
#pragma unroll
    for (int f = 0; f < 16; f++)
#pragma unroll
        for (int c = 0; c < 4; c++) o[f][c] = 0.f;

    int qa = q0 + wid * 16 + g4;
    int qb = qa + 8;
    uint32_t aoffQ = (uint32_t)((wid * 16 + (l & 15)) * ASTR + ((l >> 4) << 4));
    uint32_t koffB = (uint32_t)(((l & 7) + ((l >> 4) << 3)) * ASTR + (((l >> 3) & 1) << 4));
    uint32_t voffB = (uint32_t)((l & 15) * ASTR + ((l >> 4) << 4));

    float sA[16][4], sB[16][4];

#define QK_COMPUTE(SN, kbuf, blo_, bhi_) do {                                        \
    _Pragma("unroll") for (int f = 0; f < 16; f++)                                   \
        _Pragma("unroll") for (int c = 0; c < 4; c++) SN[f][c] = 0.f;                \
    _Pragma("unroll") for (int ks = 0; ks < 8; ks++) {                               \
        uint32_t q0r, q1r, q2r, q3r;                                                 \
        LDSM4(q0r, q1r, q2r, q3r, sQ + aoffQ + ks * 32);                             \
        _Pragma("unroll") for (int nt = 0; nt < 8; nt++) {                           \
            if (nt < (blo_) || nt > (bhi_)) continue;                                \
            uint32_t k0, k1, k2, k3;                                                 \
            LDSM4(k0, k1, k2, k3, (kbuf) + koffB + (uint32_t)(nt * 16 * ASTR) + ks * 32); \
            float* c0 = SN[2 * nt];                                                  \
            float* c1 = SN[2 * nt + 1];                                              \
            MMA_F16(c0[0], c0[1], c0[2], c0[3], q0r, q1r, q2r, q3r, k0, k1);         \
            MMA_F16(c1[0], c1[1], c1[2], c1[3], q0r, q1r, q2r, q3r, k2, k3);         \
        }                                                                            \
    }                                                                                \
} while (0)

    cp_wait1();
    __syncthreads();
    {
        int blo0 = has_edge ? wid : 0;
        int bhi0 = (kt0 == kt1) ? wid : 7;
        QK_COMPUTE(sA, sK[kt0 & 1], blo0, bhi0);
    }

#define TILE_ITER(SC, SN, i) do {                                                    \
    int bbC  = (i) & 1;                                                              \
    int ks0C = (i) << 7;                                                             \
    int bloC = ((i) == kt0 && has_edge) ? wid : 0;                                   \
    int bhiC = ((i) == kt1) ? wid : 7;                                               \
    cp_wait0();                                                                      \
    __syncthreads();                                                                 \
    if ((i) < kt1) {                                                                 \
        if ((i) + 2 <= kt1)                                                          \
            a_load_mat(sK[(i) & 1], g_kk + kvbase + ((size_t)((i) + 2) << 7) * 512, 512, tid); \
        a_load_mat(sV[((i) + 1) & 1], g_vv + kvbase + ((size_t)((i) + 1) << 7) * 512, 512, tid); \
        cp_commit();                                                                 \
        int bhiN = ((i) + 1 == kt1) ? wid : 7;                                       \
        QK_COMPUTE(SN, sK[((i) + 1) & 1], 0, bhiN);                                  \
    }                                                                                \
    {                                                                                \
        int kc0 = ks0C + 2 * t4;                                                     \
        _Pragma("unroll") for (int f = 0; f < 16; f++) {                             \
            int k0g = kc0 + 8 * f;                                                   \
            int k1g = k0g + 1;                                                       \
            SC[f][0] = ((k0g <= qa) && (qa - k0g <= WIN_)) ? SC[f][0] : -1e30f;      \
            SC[f][1] = ((k1g <= qa) && (qa - k1g <= WIN_)) ? SC[f][1] : -1e30f;      \
            SC[f][2] = ((k0g <= qb) && (qb - k0g <= WIN_)) ? SC[f][2] : -1e30f;      \
            SC[f][3] = ((k1g <= qb) && (qb - k1g <= WIN_)) ? SC[f][3] : -1e30f;      \
        }                                                                            \
    }                                                                                \
    {                                                                                \
        float pa[16], pb[16];                                                        \
        _Pragma("unroll") for (int f = 0; f < 16; f++) {                             \
            pa[f] = fmaxf(SC[f][0], SC[f][1]);                                       \
            pb[f] = fmaxf(SC[f][2], SC[f][3]);                                       \
        }                                                                            \
        _Pragma("unroll") for (int st = 8; st > 0; st >>= 1)                         \
            _Pragma("unroll") for (int j = 0; j < 16; j++) if (j < st) {             \
                pa[j] = fmaxf(pa[j], pa[j + st]);                                    \
                pb[j] = fmaxf(pb[j], pb[j + st]);                                    \
            }                                                                        \
        float ra = pa[0], rb = pb[0];                                                \
        ra = fmaxf(ra, __shfl_xor_sync(0xffffffffu, ra, 1));                         \
        ra = fmaxf(ra, __shfl_xor_sync(0xffffffffu, ra, 2));                         \
        rb = fmaxf(rb, __shfl_xor_sync(0xffffffffu, rb, 1));                         \
        rb = fmaxf(rb, __shfl_xor_sync(0xffffffffu, rb, 2));                         \
        float nm_a = fmaxf(m_a, ra), nm_b = fmaxf(m_b, rb);                          \
        float rsc_a = fexp2(m_a - nm_a), rsc_b = fexp2(m_b - nm_b);                  \
        m_a = nm_a; m_b = nm_b;                                                      \
        _Pragma("unroll") for (int f = 0; f < 16; f++) {                             \
            SC[f][0] = fexp2(SC[f][0] - m_a);                                        \
            SC[f][1] = fexp2(SC[f][1] - m_a);                                        \
            SC[f][2] = fexp2(SC[f][2] - m_b);                                        \
            SC[f][3] = fexp2(SC[f][3] - m_b);                                        \
            pa[f] = SC[f][0] + SC[f][1];                                             \
            pb[f] = SC[f][2] + SC[f][3];                                             \
        }                                                                            \
        _Pragma("unroll") for (int st = 8; st > 0; st >>= 1)                         \
            _Pragma("unroll") for (int j = 0; j < 16; j++) if (j < st) {             \
                pa[j] += pa[j + st];                                                 \
                pb[j] += pb[j + st];                                                 \
            }                                                                        \
        float sum_a = pa[0], sum_b = pb[0];                                          \
        sum_a += __shfl_xor_sync(0xffffffffu, sum_a, 1);                             \
        sum_a += __shfl_xor_sync(0xffffffffu, sum_a, 2);                             \
        sum_b += __shfl_xor_sync(0xffffffffu, sum_b, 1);                             \
        sum_b += __shfl_xor_sync(0xffffffffu, sum_b, 2);                             \
        l_a = l_a * rsc_a + sum_a;                                                   \
        l_b = l_b * rsc_b + sum_b;                                                   \
        _Pragma("unroll") for (int f = 0; f < 16; f++) {                             \
            o[f][0] *= rsc_a; o[f][1] *= rsc_a;                                      \
            o[f][2] *= rsc_b; o[f][3] *= rsc_b;                                      \
        }                                                                            \
    }                                                                                \
    _Pragma("unroll") for (int kc = 0; kc < 8; kc++) {                               \
        if (kc < bloC || kc > bhiC) continue;                                        \
        float* f0 = SC[2 * kc];                                                      \
        float* f1 = SC[2 * kc + 1];                                                  \
        uint32_t ph0 = packh(f0[0], f0[1]);                                          \
        uint32_t ph1 = packh(f0[2], f0[3]);                                          \
        uint32_t ph2 = packh(f1[0], f1[1]);                                          \
        uint32_t ph3 = packh(f1[2], f1[3]);                                          \
        _Pragma("unroll") for (int nt = 0; nt < 8; nt++) {                           \
            uint32_t v0, v1, v2, v3;                                                 \
            LDSM4T(v0, v1, v2, v3, sV[bbC] + voffB + (uint32_t)(kc * 16 * ASTR) + nt * 32); \
            float* c0 = o[2 * nt];                                                   \
            float* c1 = o[2 * nt + 1];                                               \
            MMA_F16(c0[0], c0[1], c0[2], c0[3], ph0, ph1, ph2, ph3, v0, v1);         \
            MMA_F16(c1[0], c1[1], c1[2], c1[3], ph0, ph1, ph2, ph3, v2, v3);         \
        }                                                                            \
    }                                                                                \
} while (0)

    for (int i = kt0, par = 0; i <= kt1; i++, par ^= 1) {
        if (par == 0) TILE_ITER(sA, sB, i);
        else          TILE_ITER(sB, sA, i);
    }

    float ia = 1.f / l_a, ib = 1.f / l_b;
    size_t rowa = (size_t)(b * S_) + qa;
    size_t rowb = (size_t)(b * S_) + qb;
    int colb = h * HD_ + 2 * t4;
#pragma unroll
    for (int f = 0; f < 16; f++) {
        int col = colb + 8 * f;
        *(uint32_t*)&g_oo[rowa * D_ + col] = packh(o[f][0] * ia, o[f][1] * ia);
        *(uint32_t*)&g_oo[rowb * D_ + col] = packh(o[f][2] * ib, o[f][3] * ib);
    }
}

// =================================================================================
// launch
// =================================================================================
extern "C" void kernel_launch(void* const* d_in, const int* in_sizes, int n_in,
                              void* d_out, int out_size) {
    const float* x  = (const float*)d_in[0];
    const float* Wq = (const float*)d_in[1];
    const float* Wk = (const float*)d_in[2];
    const float* Wv = (const float*)d_in[3];
    const float* Wo = (const float*)d_in[4];
    const float* qw = (const float*)d_in[5];
    const float* kw = (const float*)d_in[6];
    const float* cs = (const float*)d_in[7];
    const float* sn = (const float*)d_in[8];

    __half *ax, *wqkvT, *woT, *oo;
    cudaGetSymbolAddress((void**)&ax, g_ax);
    cudaGetSymbolAddress((void**)&wqkvT, g_wqkvT);
    cudaGetSymbolAddress((void**)&woT, g_woT);
    cudaGetSymbolAddress((void**)&oo, g_oo);

    const int M = MROWS;

    cudaFuncSetAttribute(bgemm<0>, cudaFuncAttributeMaxDynamicSharedMemorySize, GEMM_SMEM);
    cudaFuncSetAttribute(bgemm<1>, cudaFuncAttributeMaxDynamicSharedMemorySize, GEMM_SMEM);
    cudaFuncSetAttribute(attn_kernel, cudaFuncAttributeMaxDynamicSharedMemorySize, ATTN_SMEM);

    // prep
    {
        int n4 = M * D_ / 4;
        aconv<<<(n4 + 255) / 256, 256>>>((const float4*)x, ax, n4);
    }
    wconv_all<<<10240, dim3(32, 8)>>>(Wq, Wk, Wv, Wo, wqkvT, woT);

    // fused QKV projection (N = 3072, 256-wide tiles)
    bgemm<1><<<dim3(3072 / 256, M / 128), 256, GEMM_SMEM>>>(ax, wqkvT, nullptr, M, 3072, D_);

    // RMSNorm + RoPE
    {
        int nwarps = B_ * S_ * (HQ_ + HKV_);
        int nblocks = (nwarps * 32 + 255) / 256;
        norm_rope_kernel<<<nblocks, 256>>>(qw, kw, cs, sn);
    }

    // attention
    attn_kernel<<<dim3(S_ / 128, HQ_, B_), 256, ATTN_SMEM>>>();

    // output projection (N = 2048, 256-wide tiles)
    bgemm<0><<<dim3(D_ / 256, M / 128), 256, GEMM_SMEM>>>(oo, woT, (float*)d_out, M, D_, D_);
}

// round 12
// speedup vs baseline: 1.4133x; 1.4133x over previous
#include <cuda_runtime.h>
#include <cuda_fp16.h>
#include <math.h>
#include <stdint.h>

#define B_   2
#define S_   2048
#define D_   2048
#define HQ_  16
#define HKV_ 4
#define HD_  128
#define WIN_ 1024
#define EPS_ 1e-8f
#define MROWS (B_ * S_)    // 4096

// ---------------- scratch (device globals) ----------------
__device__ float g_q[MROWS * HQ_ * HD_];
__device__ float g_k[MROWS * HKV_ * HD_];

__device__ __half g_qq[MROWS * D_];
__device__ __half g_kk[MROWS * 512];
__device__ __half g_vv[MROWS * 512];
__device__ __half g_oo[MROWS * D_];

__device__ __half g_ax[MROWS * D_];
__device__ __half g_wqkvT[3072 * D_];
__device__ __half g_woT[D_ * D_];

__device__ __forceinline__ uint32_t smem_u32(const void* p) {
    uint32_t a;
    asm("{ .reg .u64 t; cvta.to.shared.u64 t, %1; cvt.u32.u64 %0, t; }" : "=r"(a) : "l"(p));
    return a;
}

#define LDSM4(r0, r1, r2, r3, addr) \
    asm volatile("ldmatrix.sync.aligned.m8n8.x4.shared.b16 {%0,%1,%2,%3}, [%4];" \
                 : "=r"(r0), "=r"(r1), "=r"(r2), "=r"(r3) : "r"(addr))
#define LDSM4T(r0, r1, r2, r3, addr) \
    asm volatile("ldmatrix.sync.aligned.m8n8.x4.trans.shared.b16 {%0,%1,%2,%3}, [%4];" \
                 : "=r"(r0), "=r"(r1), "=r"(r2), "=r"(r3) : "r"(addr))

#define MMA_F16(c0, c1, c2, c3, a0, a1, a2, a3, b0, b1) \
    asm volatile("mma.sync.aligned.m16n8k16.row.col.f32.f16.f16.f32 " \
                 "{%0,%1,%2,%3}, {%4,%5,%6,%7}, {%8,%9}, {%0,%1,%2,%3};" \
                 : "+f"(c0), "+f"(c1), "+f"(c2), "+f"(c3) \
                 : "r"(a0), "r"(a1), "r"(a2), "r"(a3), "r"(b0), "r"(b1))

__device__ __forceinline__ void cp16(uint32_t dst, const void* src) {
    asm volatile("cp.async.cg.shared.global [%0], [%1], 16;" :: "r"(dst), "l"(src));
}
__device__ __forceinline__ void cp_commit() { asm volatile("cp.async.commit_group;"); }
__device__ __forceinline__ void cp_wait1() { asm volatile("cp.async.wait_group 1;"); }
__device__ __forceinline__ void cp_wait0() { asm volatile("cp.async.wait_group 0;"); }

__device__ __forceinline__ uint32_t packh(float lo, float hi) {
    __half2 h = __floats2half2_rn(lo, hi);
    return *(uint32_t*)&h;
}

__device__ __forceinline__ float fexp2(float x) {
    float r;
    asm("ex2.approx.ftz.f32 %0, %1;" : "=f"(r) : "f"(x));
    return r;
}

// =================================================================================
// prep kernels
// =================================================================================
__global__ void aconv(const float4* __restrict__ src, __half* __restrict__ dst, int n4) {
    int i = blockIdx.x * blockDim.x + threadIdx.x;
    if (i >= n4) return;
    float4 v = src[i];
    uint32_t* dp = (uint32_t*)(dst + (size_t)i * 4);
    dp[0] = packh(v.x, v.y);
    dp[1] = packh(v.z, v.w);
}

// All 4 weight transposes in ONE launch (regions decoded from blockIdx).
__global__ void wconv_all(const float* __restrict__ Wq, const float* __restrict__ Wk,
                          const float* __restrict__ Wv, const float* __restrict__ Wo,
                          __half* __restrict__ wqkvT, __half* __restrict__ woT) {
    __shared__ float t[32][33];
    int bt = blockIdx.x;
    const float* W;
    __half* T;
    int N, ntiles_x;
    if (bt < 4096)       { W = Wq; T = wqkvT;                          N = 2048; ntiles_x = 64; }
    else if (bt < 5120)  { W = Wk; T = wqkvT + (size_t)2048 * D_; bt -= 4096; N = 512; ntiles_x = 16; }
    else if (bt < 6144)  { W = Wv; T = wqkvT + (size_t)2560 * D_; bt -= 5120; N = 512; ntiles_x = 16; }
    else                 { W = Wo; T = woT;                      bt -= 6144; N = 2048; ntiles_x = 64; }
    int n0 = (bt % ntiles_x) * 32, k0 = (bt / ntiles_x) * 32;
    int tx = threadIdx.x, ty = threadIdx.y;
#pragma unroll
    for (int i = 0; i < 4; i++) {
        int k = ty + i * 8;
        t[k][tx] = W[(size_t)(k0 + k) * N + n0 + tx];
    }
    __syncthreads();
#pragma unroll
    for (int i = 0; i < 4; i++) {
        int r = ty + i * 8;
        T[(size_t)(n0 + r) * D_ + k0 + tx] = __float2half_rn(t[tx][r]);
    }
}

// =================================================================================
// mma.sync fp16 GEMM (R10-proven): 128x128x64, 3-stage cp.async, 8 warps (2m x 4n).
// MODE 0: fp32 C.   MODE 1: fused QKV epilogue (N=3072; routes to g_q/g_k/g_vv).
// =================================================================================
#define GSTRIDE 72
#define GTILE   (128 * GSTRIDE * 2)     // 18432 B
#define GSTAGE  (2 * GTILE)             // 36864 B
#define GEMM_SMEM (3 * GSTAGE)          // 110592 B

__device__ __forceinline__ void g_load_stage(
    uint32_t sdst, const __half* __restrict__ A, const __half* __restrict__ Bt,
    int m0, int n0, int kc, int K, int tid) {
    const __half* gb[2] = { A + (size_t)m0 * K, Bt + (size_t)n0 * K };
#pragma unroll
    for (int mat = 0; mat < 2; mat++) {
        const __half* g = gb[mat] + kc * 64;
        uint32_t db = sdst + mat * GTILE;
#pragma unroll
        for (int i = 0; i < 4; i++) {
            int ch  = tid + 256 * i;
            int row = ch >> 3;
            int off = (ch & 7) * 8;
            cp16(db + row * (GSTRIDE * 2) + off * 2, g + (size_t)row * K + off);
        }
    }
}

template<int MODE>
__global__ __launch_bounds__(256, 1)
void bgemm(const __half* __restrict__ A, const __half* __restrict__ Bt,
           float* __restrict__ C, int M, int N, int K) {
    extern __shared__ char sm[];
    uint32_t sb = smem_u32(sm);
    int tid = threadIdx.x, lane = tid & 31, wid = tid >> 5;
    int n0 = blockIdx.x * 128, m0 = blockIdx.y * 128;
    int wm = (wid >> 2) * 64;
    int wn = (wid & 3) * 32;

    float acc[4][4][4];
#pragma unroll
    for (int i = 0; i < 4; i++)
#pragma unroll
        for (int j = 0; j < 4; j++)
#pragma unroll
            for (int c = 0; c < 4; c++) acc[i][j][c] = 0.f;

    int a_row = wm + (lane & 15);
    int a_kb  = (lane >> 4) * 16;
    int b_row = wn + (lane & 7) + ((lane >> 4) << 3);
    int b_kb  = ((lane >> 3) & 1) * 16;
    uint32_t aoff = (uint32_t)(a_row * (GSTRIDE * 2) + a_kb);
    uint32_t boff = (uint32_t)(b_row * (GSTRIDE * 2) + b_kb);

    int nk = K >> 6;
    g_load_stage(sb, A, Bt, m0, n0, 0, K, tid);
    cp_commit();
    g_load_stage(sb + GSTAGE, A, Bt, m0, n0, 1, K, tid);
    cp_commit();

    for (int kt = 0; kt < nk; kt++) {
        if (kt + 1 < nk) cp_wait1(); else cp_wait0();
        __syncthreads();

        uint32_t st = sb + (kt % 3) * GSTAGE;
#pragma unroll
        for (int ks = 0; ks < 4; ks++) {
            uint32_t ah[4][4];
#pragma unroll
            for (int mt = 0; mt < 4; mt++) {
                uint32_t adr = st + aoff + mt * 16 * (GSTRIDE * 2) + ks * 32;
                LDSM4(ah[mt][0], ah[mt][1], ah[mt][2], ah[mt][3], adr);
            }
            uint32_t bh[4][2];
#pragma unroll
            for (int nt2 = 0; nt2 < 2; nt2++) {
                uint32_t adr = st + GTILE + boff + nt2 * 16 * (GSTRIDE * 2) + ks * 32;
                uint32_t r0, r1, r2, r3;
                LDSM4(r0, r1, r2, r3, adr);
                bh[nt2 * 2][0] = r0; bh[nt2 * 2][1] = r1;
                bh[nt2 * 2 + 1][0] = r2; bh[nt2 * 2 + 1][1] = r3;
            }
#pragma unroll
            for (int mt = 0; mt < 4; mt++)
#pragma unroll
                for (int nt = 0; nt < 4; nt++) {
                    float* c = acc[mt][nt];
                    MMA_F16(c[0], c[1], c[2], c[3],
                            ah[mt][0], ah[mt][1], ah[mt][2], ah[mt][3],
                            bh[nt][0], bh[nt][1]);
                }
        }

        if (kt + 2 < nk) {
            g_load_stage(sb + ((kt + 2) % 3) * GSTAGE, A, Bt, m0, n0, kt + 2, K, tid);
            cp_commit();
        }
    }

#pragma unroll
    for (int mt = 0; mt < 4; mt++) {
#pragma unroll
        for (int nt = 0; nt < 4; nt++) {
            int r = m0 + wm + mt * 16 + (lane >> 2);
            int cc = n0 + wn + nt * 8 + (lane & 3) * 2;
            float* c = acc[mt][nt];
            if (MODE == 1) {
                if (cc < 2048) {
                    *(float2*)&g_q[(size_t)r * 2048 + cc]       = make_float2(c[0], c[1]);
                    *(float2*)&g_q[(size_t)(r + 8) * 2048 + cc] = make_float2(c[2], c[3]);
                } else if (cc < 2560) {
                    int c2 = cc - 2048;
                    *(float2*)&g_k[(size_t)r * 512 + c2]       = make_float2(c[0], c[1]);
                    *(float2*)&g_k[(size_t)(r + 8) * 512 + c2] = make_float2(c[2], c[3]);
                } else {
                    int c2 = cc - 2560;
                    *(uint32_t*)&g_vv[(size_t)r * 512 + c2]       = packh(c[0], c[1]);
                    *(uint32_t*)&g_vv[(size_t)(r + 8) * 512 + c2] = packh(c[2], c[3]);
                }
            } else {
                *(float2*)&C[(size_t)r * N + cc]       = make_float2(c[0], c[1]);
                *(float2*)&C[(size_t)(r + 8) * N + cc] = make_float2(c[2], c[3]);
            }
        }
    }
}

// =================================================================================
// RMSNorm + RoPE (unchanged)
// =================================================================================
__global__ void norm_rope_kernel(const float* __restrict__ qw,
                                 const float* __restrict__ kw,
                                 const float* __restrict__ cos_t,
                                 const float* __restrict__ sin_t) {
    int wid  = (blockIdx.x * blockDim.x + threadIdx.x) >> 5;
    int lane = threadIdx.x & 31;
    const int NQ   = B_ * S_ * HQ_;
    const int NTOT = NQ + B_ * S_ * HKV_;
    if (wid >= NTOT) return;

    const float FOLD = 0.08838834764831845f * 1.4426950408889634f;

    bool isq = wid < NQ;
    const float* base;
    int s;
    const float* w;
    float fold;
    __half* out;
    if (isq) {
        base = g_q + (size_t)wid * HD_;
        out  = g_qq + (size_t)wid * HD_;
        s = (wid / HQ_) % S_;
        w = qw;
        fold = FOLD;
    } else {
        int r = wid - NQ;
        base = g_k + (size_t)r * HD_;
        out  = g_kk + (size_t)r * HD_;
        s = (r / HKV_) % S_;
        w = kw;
        fold = 1.0f;
    }

    float v0 = base[lane], v1 = base[lane + 32], v2 = base[lane + 64], v3 = base[lane + 96];
    float ss = v0 * v0 + v1 * v1 + v2 * v2 + v3 * v3;
#pragma unroll
    for (int o = 16; o > 0; o >>= 1) ss += __shfl_xor_sync(0xffffffff, ss, o);
    float inv = rsqrtf(ss * (1.0f / HD_) + EPS_);

    float x0 = v0 * inv * (1.f + w[lane]);
    float x1 = v1 * inv * (1.f + w[lane + 32]);
    float x2 = v2 * inv * (1.f + w[lane + 64]);
    float x3 = v3 * inv * (1.f + w[lane + 96]);

    const float* cr = cos_t + (size_t)s * HD_;
    const float* sr = sin_t + (size_t)s * HD_;
    out[lane]      = __float2half_rn((x0 * cr[lane]      - x2 * sr[lane])      * fold);
    out[lane + 32] = __float2half_rn((x1 * cr[lane + 32] - x3 * sr[lane + 32]) * fold);
    out[lane + 64] = __float2half_rn((x2 * cr[lane + 64] + x0 * sr[lane + 64]) * fold);
    out[lane + 96] = __float2half_rn((x3 * cr[lane + 96] + x1 * sr[lane + 96]) * fold);
}

// =================================================================================
// Tensor-core flash attention (R10 structure; tree-reduced softmax).
// =================================================================================
#define ASTR 272
#define AMAT (128 * ASTR)
#define ATTN_SMEM (5 * AMAT)

__device__ __forceinline__ void a_load_mat(uint32_t sdst, const __half* __restrict__ g,
                                           int rowstride, int tid) {
#pragma unroll
    for (int i = 0; i < 8; i++) {
        int ch = tid + 256 * i;
        int row = ch >> 4, c = ch & 15;
        cp16(sdst + row * ASTR + c * 16, g + (size_t)row * rowstride + c * 8);
    }
}

__global__ __launch_bounds__(256, 1)
void attn_kernel() {
    extern __shared__ char sm[];
    uint32_t sb = smem_u32(sm);
    const uint32_t sQ = sb;
    const uint32_t sK[2] = { sb + 1 * AMAT, sb + 2 * AMAT };
    const uint32_t sV[2] = { sb + 3 * AMAT, sb + 4 * AMAT };

    int tid = threadIdx.x, l = tid & 31, wid = tid >> 5;
    int qt = gridDim.x - 1 - blockIdx.x;
    int h = blockIdx.y, b = blockIdx.z;
    int q0 = qt * 128;
    int kvh = h >> 2;
    int g4 = l >> 2, t4 = l & 3;

    int lo = q0 - WIN_; if (lo < 0) lo = 0;
    int kt0 = lo >> 7, kt1 = q0 >> 7;
    bool has_edge = (q0 >= WIN_);

    const size_t kvbase = (size_t)(b * S_) * 512 + kvh * HD_;

    a_load_mat(sQ, g_qq + ((size_t)(b * S_ + q0)) * D_ + h * HD_, D_, tid);
    a_load_mat(sK[kt0 & 1], g_kk + kvbase + ((size_t)kt0 << 7) * 512, 512, tid);
    cp_commit();
    a_load_mat(sV[kt0 & 1], g_vv + kvbase + ((size_t)kt0 << 7) * 512, 512, tid);
    if (kt0 < kt1)
        a_load_mat(sK[(kt0 + 1) & 1], g_kk + kvbase + ((size_t)(kt0 + 1) << 7) * 512, 512, tid);
    cp_commit();

    float m_a = 0.f, m_b = 0.f, l_a = 0.f, l_b = 0.f;
    float o[16][4];
#pragma unroll
    for (int f = 0; f < 16; f++)
#pragma unroll
        for (int c = 0; c < 4; c++) o[f][c] = 0.f;

    int qa = q0 + wid * 16 + g4;
    int qb = qa + 8;
    uint32_t aoffQ = (uint32_t)((wid * 16 + (l & 15)) * ASTR + ((l >> 4) << 4));
    uint32_t koffB = (uint32_t)(((l & 7) + ((l >> 4) << 3)) * ASTR + (((l >> 3) & 1) << 4));
    uint32_t voffB = (uint32_t)((l & 15) * ASTR + ((l >> 4) << 4));

    float sA[16][4], sB[16][4];

#define QK_COMPUTE(SN, kbuf, blo_, bhi_) do {                                        \
    _Pragma("unroll") for (int f = 0; f < 16; f++)                                   \
        _Pragma("unroll") for (int c = 0; c < 4; c++) SN[f][c] = 0.f;                \
    _Pragma("unroll") for (int ks = 0; ks < 8; ks++) {                               \
        uint32_t q0r, q1r, q2r, q3r;                                                 \
        LDSM4(q0r, q1r, q2r, q3r, sQ + aoffQ + ks * 32);                             \
        _Pragma("unroll") for (int nt = 0; nt < 8; nt++) {                           \
            if (nt < (blo_) || nt > (bhi_)) continue;                                \
            uint32_t k0, k1, k2, k3;                                                 \
            LDSM4(k0, k1, k2, k3, (kbuf) + koffB + (uint32_t)(nt * 16 * ASTR) + ks * 32); \
            float* c0 = SN[2 * nt];                                                  \
            float* c1 = SN[2 * nt + 1];                                              \
            MMA_F16(c0[0], c0[1], c0[2], c0[3], q0r, q1r, q2r, q3r, k0, k1);         \
            MMA_F16(c1[0], c1[1], c1[2], c1[3], q0r, q1r, q2r, q3r, k2, k3);         \
        }                                                                            \
    }                                                                                \
} while (0)

    cp_wait1();
    __syncthreads();
    {
        int blo0 = has_edge ? wid : 0;
        int bhi0 = (kt0 == kt1) ? wid : 7;
        QK_COMPUTE(sA, sK[kt0 & 1], blo0, bhi0);
    }

#define TILE_ITER(SC, SN, i) do {                                                    \
    int bbC  = (i) & 1;                                                              \
    int ks0C = (i) << 7;                                                             \
    int bloC = ((i) == kt0 && has_edge) ? wid : 0;                                   \
    int bhiC = ((i) == kt1) ? wid : 7;                                               \
    cp_wait0();                                                                      \
    __syncthreads();                                                                 \
    if ((i) < kt1) {                                                                 \
        if ((i) + 2 <= kt1)                                                          \
            a_load_mat(sK[(i) & 1], g_kk + kvbase + ((size_t)((i) + 2) << 7) * 512, 512, tid); \
        a_load_mat(sV[((i) + 1) & 1], g_vv + kvbase + ((size_t)((i) + 1) << 7) * 512, 512, tid); \
        cp_commit();                                                                 \
        int bhiN = ((i) + 1 == kt1) ? wid : 7;                                       \
        QK_COMPUTE(SN, sK[((i) + 1) & 1], 0, bhiN);                                  \
    }                                                                                \
    {                                                                                \
        int kc0 = ks0C + 2 * t4;                                                     \
        _Pragma("unroll") for (int f = 0; f < 16; f++) {                             \
            int k0g = kc0 + 8 * f;                                                   \
            int k1g = k0g + 1;                                                       \
            SC[f][0] = ((k0g <= qa) && (qa - k0g <= WIN_)) ? SC[f][0] : -1e30f;      \
            SC[f][1] = ((k1g <= qa) && (qa - k1g <= WIN_)) ? SC[f][1] : -1e30f;      \
            SC[f][2] = ((k0g <= qb) && (qb - k0g <= WIN_)) ? SC[f][2] : -1e30f;      \
            SC[f][3] = ((k1g <= qb) && (qb - k1g <= WIN_)) ? SC[f][3] : -1e30f;      \
        }                                                                            \
    }                                                                                \
    {                                                                                \
        float pa[16], pb[16];                                                        \
        _Pragma("unroll") for (int f = 0; f < 16; f++) {                             \
            pa[f] = fmaxf(SC[f][0], SC[f][1]);                                       \
            pb[f] = fmaxf(SC[f][2], SC[f][3]);                                       \
        }                                                                            \
        _Pragma("unroll") for (int st = 8; st > 0; st >>= 1)                         \
            _Pragma("unroll") for (int j = 0; j < 16; j++) if (j < st) {             \
                pa[j] = fmaxf(pa[j], pa[j + st]);                                    \
                pb[j] = fmaxf(pb[j], pb[j + st]);                                    \
            }                                                                        \
        float ra = pa[0], rb = pb[0];                                                \
        ra = fmaxf(ra, __shfl_xor_sync(0xffffffffu, ra, 1));                         \
        ra = fmaxf(ra, __shfl_xor_sync(0xffffffffu, ra, 2));                         \
        rb = fmaxf(rb, __shfl_xor_sync(0xffffffffu, rb, 1));                         \
        rb = fmaxf(rb, __shfl_xor_sync(0xffffffffu, rb, 2));                         \
        float nm_a = fmaxf(m_a, ra), nm_b = fmaxf(m_b, rb);                          \
        float rsc_a = fexp2(m_a - nm_a), rsc_b = fexp2(m_b - nm_b);                  \
        m_a = nm_a; m_b = nm_b;                                                      \
        _Pragma("unroll") for (int f = 0; f < 16; f++) {                             \
            SC[f][0] = fexp2(SC[f][0] - m_a);                                        \
            SC[f][1] = fexp2(SC[f][1] - m_a);                                        \
            SC[f][2] = fexp2(SC[f][2] - m_b);                                        \
            SC[f][3] = fexp2(SC[f][3] - m_b);                                        \
            pa[f] = SC[f][0] + SC[f][1];                                             \
            pb[f] = SC[f][2] + SC[f][3];                                             \
        }                                                                            \
        _Pragma("unroll") for (int st = 8; st > 0; st >>= 1)                         \
            _Pragma("unroll") for (int j = 0; j < 16; j++) if (j < st) {             \
                pa[j] += pa[j + st];                                                 \
                pb[j] += pb[j + st];                                                 \
            }                                                                        \
        float sum_a = pa[0], sum_b = pb[0];                                          \
        sum_a += __shfl_xor_sync(0xffffffffu, sum_a, 1);                             \
        sum_a += __shfl_xor_sync(0xffffffffu, sum_a, 2);                             \
        sum_b += __shfl_xor_sync(0xffffffffu, sum_b, 1);                             \
        sum_b += __shfl_xor_sync(0xffffffffu, sum_b, 2);                             \
        l_a = l_a * rsc_a + sum_a;                                                   \
        l_b = l_b * rsc_b + sum_b;                                                   \
        _Pragma("unroll") for (int f = 0; f < 16; f++) {                             \
            o[f][0] *= rsc_a; o[f][1] *= rsc_a;                                      \
            o[f][2] *= rsc_b; o[f][3] *= rsc_b;                                      \
        }                                                                            \
    }                                                                                \
    _Pragma("unroll") for (int kc = 0; kc < 8; kc++) {                               \
        if (kc < bloC || kc > bhiC) continue;                                        \
        float* f0 = SC[2 * kc];                                                      \
        float* f1 = SC[2 * kc + 1];                                                  \
        uint32_t ph0 = packh(f0[0], f0[1]);                                          \
        uint32_t ph1 = packh(f0[2], f0[3]);                                          \
        uint32_t ph2 = packh(f1[0], f1[1]);                                          \
        uint32_t ph3 = packh(f1[2], f1[3]);                                          \
        _Pragma("unroll") for (int nt = 0; nt < 8; nt++) {                           \
            uint32_t v0, v1, v2, v3;                                                 \
            LDSM4T(v0, v1, v2, v3, sV[bbC] + voffB + (uint32_t)(kc * 16 * ASTR) + nt * 32); \
            float* c0 = o[2 * nt];                                                   \
            float* c1 = o[2 * nt + 1];                                               \
            MMA_F16(c0[0], c0[1], c0[2], c0[3], ph0, ph1, ph2, ph3, v0, v1);         \
            MMA_F16(c1[0], c1[1], c1[2], c1[3], ph0, ph1, ph2, ph3, v2, v3);         \
        }                                                                            \
    }                                                                                \
} while (0)

    for (int i = kt0, par = 0; i <= kt1; i++, par ^= 1) {
        if (par == 0) TILE_ITER(sA, sB, i);
        else          TILE_ITER(sB, sA, i);
    }

    float ia = 1.f / l_a, ib = 1.f / l_b;
    size_t rowa = (size_t)(b * S_) + qa;
    size_t rowb = (size_t)(b * S_) + qb;
    int colb = h * HD_ + 2 * t4;
#pragma unroll
    for (int f = 0; f < 16; f++) {
        int col = colb + 8 * f;
        *(uint32_t*)&g_oo[rowa * D_ + col] = packh(o[f][0] * ia, o[f][1] * ia);
        *(uint32_t*)&g_oo[rowb * D_ + col] = packh(o[f][2] * ib, o[f][3] * ib);
    }
}

// =================================================================================
// launch
// =================================================================================
extern "C" void kernel_launch(void* const* d_in, const int* in_sizes, int n_in,
                              void* d_out, int out_size) {
    const float* x  = (const float*)d_in[0];
    const float* Wq = (const float*)d_in[1];
    const float* Wk = (const float*)d_in[2];
    const float* Wv = (const float*)d_in[3];
    const float* Wo = (const float*)d_in[4];
    const float* qw = (const float*)d_in[5];
    const float* kw = (const float*)d_in[6];
    const float* cs = (const float*)d_in[7];
    const float* sn = (const float*)d_in[8];

    __half *ax, *wqkvT, *woT, *oo;
    cudaGetSymbolAddress((void**)&ax, g_ax);
    cudaGetSymbolAddress((void**)&wqkvT, g_wqkvT);
    cudaGetSymbolAddress((void**)&woT, g_woT);
    cudaGetSymbolAddress((void**)&oo, g_oo);

    const int M = MROWS;

    cudaFuncSetAttribute(bgemm<0>, cudaFuncAttributeMaxDynamicSharedMemorySize, GEMM_SMEM);
    cudaFuncSetAttribute(bgemm<1>, cudaFuncAttributeMaxDynamicSharedMemorySize, GEMM_SMEM);
    cudaFuncSetAttribute(attn_kernel, cudaFuncAttributeMaxDynamicSharedMemorySize, ATTN_SMEM);

    // prep
    {
        int n4 = M * D_ / 4;
        aconv<<<(n4 + 255) / 256, 256>>>((const float4*)x, ax, n4);
    }
    wconv_all<<<10240, dim3(32, 8)>>>(Wq, Wk, Wv, Wo, wqkvT, woT);

    // fused QKV projection (N = 3072, 128-wide tiles)
    bgemm<1><<<dim3(3072 / 128, M / 128), 256, GEMM_SMEM>>>(ax, wqkvT, nullptr, M, 3072, D_);

    // RMSNorm + RoPE
    {
        int nwarps = B_ * S_ * (HQ_ + HKV_);
        int nblocks = (nwarps * 32 + 255) / 256;
        norm_rope_kernel<<<nblocks, 256>>>(qw, kw, cs, sn);
    }

    // attention
    attn_kernel<<<dim3(S_ / 128, HQ_, B_), 256, ATTN_SMEM>>>();

    // output projection
    bgemm<0><<<dim3(D_ / 128, M / 128), 256, GEMM_SMEM>>>(oo, woT, (float*)d_out, M, D_, D_);
}